// round 13
// baseline (speedup 1.0000x reference)
#include <cuda_runtime.h>
#include <math.h>

#define SAC_WARMUP 365
#define PF 4

__device__ __forceinline__ float fast_lg2(float x) {
    float r; asm("lg2.approx.f32 %0, %1;" : "=f"(r) : "f"(x)); return r;
}
__device__ __forceinline__ float fast_ex2(float x) {
    float r; asm("ex2.approx.f32 %0, %1;" : "=f"(r) : "f"(x)); return r;
}
__device__ __forceinline__ float fast_rcp(float d) {
    float r; asm("rcp.approx.f32 %0, %1;" : "=f"(r) : "f"(d));
    r = r * (2.0f - d * r);
    return r;
}

template <int BC>
__global__ __launch_bounds__(128, 1)
void sac4dpl_kernel(const float* __restrict__ p_and_e,   // [T, B, 2]
                    const float* __restrict__ params,    // [B, 21]
                    float* __restrict__ out,             // [2, T-WARMUP, B]
                    int T, int Brt)
{
    const int B = (BC > 0) ? BC : Brt;
    int b = blockIdx.x * 128 + threadIdx.x;
    if (b >= B) return;

    const float lo[21] = {0.1f, 0.0f, 0.0f, 10.0f, 10.0f, 50.0f, 10.0f, 50.0f,
                          0.0f, 0.0f, 0.0f, 5.0f, 1.0f, 0.1f, 0.01f, 0.001f,
                          0.5f, 0.95f, 0.98f, 0.0f, 0.0f};
    const float hi[21] = {1.2f, 0.1f, 0.3f, 100.0f, 100.0f, 400.0f, 100.0f, 1000.0f,
                          0.3f, 0.5f, 0.1f, 350.0f, 4.0f, 0.5f, 0.35f, 0.05f,
                          0.9f, 0.998f, 0.998f, 1.0f, 0.5f};
    float pr[21];
#pragma unroll
    for (int i = 0; i < 21; i++)
        pr[i] = lo[i] + params[(size_t)b * 21 + i] * (hi[i] - lo[i]);

    const float kc    = pr[0],  pctim = pr[1],  adimp = pr[2];
    const float uztwm = pr[3],  uzfwm = pr[4],  lztwm = pr[5];
    const float lzfsm = pr[6],  lzfpm = pr[7];
    const float pfree = pr[9],  riva  = pr[10];
    const float zperc = pr[11], rexp  = pr[12], uzk = pr[13];
    const float lzsk  = pr[14], lzpk  = pr[15];
    const float ci    = pr[16], cgs   = pr[17], cgp = pr[18];
    const float ke    = pr[19], xe    = pr[20];

    const float r_uztwm = 1.0f / uztwm;
    const float r_lztwm = 1.0f / lztwm;
    const float r_ulz   = 1.0f / (uztwm + lztwm);
    const float r_lzfsm = 1.0f / lzfsm;
    const float r_lzfpm = 1.0f / lzfpm;
    const float sfm     = lzfsm + lzfpm;
    const float lzsum   = sfm + lztwm;
    const float r_lzsum = 1.0f / lzsum;
    const float uzsum   = uztwm + uzfwm;
    const float pbase   = lzfsm * lzsk + lzfpm * lzpk;
    const float parea   = 1.0f - pctim - adimp;
    const float fp2     = 2.0f * (lzfpm / sfm);
    const float pbu     = pbase / uzfwm;
    const float pbuz    = pbu * zperc;
    const float ci1     = (1.0f - ci)  * parea;
    const float cgs1    = (1.0f - cgs) * parea;
    const float cgp1    = (1.0f - cgp) * parea;
    const float dt      = 0.5f;
    const float mden    = ke * (1.0f - xe) + dt;
    const float c1      = (ke * xe + dt) / mden;
    const float c2      = (dt - ke * xe) / mden;
    const float c3      = (ke * (1.0f - xe) - dt) / mden;

    // ---- initial carry ----
    float auztw = 0.01f, alztw = 0.01f;
    float uztw  = 0.01f, uzfw  = 0.01f;
    float lztw  = 0.01f, lzfs  = 0.01f, lzfp = 0.01f;
    float qs = 0.01f, qi = 0.01f, qgs = 0.01f, qgp = 0.01f;
    float o1 = 0.01f;
    float i2c = (qs + qi) + (qgs + qgp);   // i1(t) == i2(t-1): carried sum
    float o2 = 0.01f, et = 0.01f;

    const float2* __restrict__ pe  = (const float2*)p_and_e + b;
    const int nout = T - SAC_WARMUP;
    float* __restrict__ qout = out + b;
    float* __restrict__ eout = out + (size_t)nout * B + b;

    float2 buf[PF];
#pragma unroll
    for (int i = 0; i < PF; i++)
        buf[i] = pe[(size_t)i * B];
    const float2* __restrict__ pe_pf = pe + (size_t)PF * B;

    // R10 body + deletion-only trims:
    //  - i1 replaced by carried i2c (i1(t) == i2(t-1))
    //  - p/e clamps dropped (inputs uniform[0,20]/[0,6], provably >= 0)
    //  - ET fold only when DO_ET (store phase)
#define SAC_BODY(cur, DO_ET)                                                   \
    do {                                                                       \
        /* ---- carry-only preamble ---- */                                    \
        float uzw_sum = uztw + uzfw;                                           \
        float lzfsp   = lzfs + lzfp;                                           \
        float uma     = auztw - uztwm;                                         \
        float aru     = alztw * r_ulz;                                         \
        float lru     = lztw  * r_ulz;                                         \
        float sfm_l   = sfm   - lzfsp;                                         \
        float lzfpm_l = lzfpm - lzfp;                                          \
        float lzfsm_l = lzfsm - lzfs;                                          \
        float gp = 1.0f - lzfp * r_lzfpm;                                      \
        float gs = 1.0f - lzfs * r_lzfsm;                                      \
        float coef = fminf(fp2 * gp * fast_rcp(gp + gs), 1.0f);                \
        float mpre = c1 * i2c + c3 * o1;     /* o2 = c2*i2 + mpre */           \
        /* ---- input-dependent chain ---- */                                  \
        float p = (cur).x;                                                     \
        float e = (cur).y;                                                     \
        float ep    = kc * e;                                                  \
        float epru  = ep * r_uztwm;                                            \
        float roimp = pctim * p;                                               \
        float ae1   = fminf(auztw, epru * auztw);                              \
        float e1    = fminf(uztw,  epru * uztw);                               \
        float ae3   = (ep - ae1) * aru;                                        \
        float pav   = fmaxf((p + uma) - ae1, 0.0f);                            \
        float almae3 = alztw - ae3;                                            \
        float adsur = pav * (almae3 * r_lztwm);                                \
        float pam   = (pav - adsur) + almae3;                                  \
        float ars   = fmaxf(pam - lztwm, 0.0f);                                \
        float auztw_n = fminf(uztwm, (auztw - ae1) + p);                       \
        float alztw_n = fminf(lztwm, pam);                                     \
        float e2  = fminf(uzfw, ep - e1);                                      \
        float e12 = e1 + e2;                                                   \
        float e3  = (ep - e12) * lru;                                          \
        float lt1 = lztw - e3;                                                 \
        if (DO_ET) {                                                           \
            float ae2 = pctim * ep;                                            \
            float e4  = riva * ep;                                             \
            et = ((ae2 + ae1) + (ae3 + e1)) + ((e2 + e3) + e4);                \
        }                                                                      \
        float uzres = p + (uzw_sum - e12);                                     \
        float rs = fmaxf(uzres - uzsum, 0.0f) * parea;                         \
        float ut = fminf(uztwm, (uztw + p) - e1);                              \
        float uf = fminf(uzfwm, uzres - ut);                                   \
        float ri = uf * uzk;                                                   \
        uf = uf - ri;                                                          \
        float lzdef = lzfsp + lt1;                                             \
        float defr  = fmaxf(1.0f - lzdef * r_lzsum, 0.0f);                     \
        float pw    = fast_ex2(rexp * fast_lg2(defr));                         \
        float perc  = (pbu + pbuz * pw) * uf;                                  \
        float rate  = fminf(perc, lzsum - lzdef);                              \
        uf = fmaxf(uf - rate, 0.0f);                                           \
        float fx    = fminf(sfm_l,                                             \
                            fmaxf(rate - (lztwm - lt1), rate * pfree));        \
        float perct = rate - fx;                                               \
        float percp = fminf(lzfpm_l, fmaxf(fx - lzfsm_l, coef * fx));          \
        float percs = fx - percp;                                              \
        float lt = fminf(lt1 + perct, lztwm);                                  \
        float ls = lzfs + percs;                                               \
        float lp = lzfp + percp;                                               \
        float rgs = ls * lzsk;  ls = ls - rgs;                                 \
        float rgp = lp * lzpk;  lp = lp - rgp;                                 \
        float qs_n = (roimp + rs) + (adsur + ars) * adimp;                     \
        float qi_n = ci  * qi  + ci1  * ri;                                    \
        float qgs_n = cgs * qgs + cgs1 * rgs;                                  \
        float qgp_n = cgp * qgp + cgp1 * rgp;                                  \
        float i2   = (qs_n + qi_n) + (qgs_n + qgp_n);                          \
        o2 = c2 * i2 + mpre;                                                   \
        i2c = i2;                                                              \
        auztw = auztw_n; alztw = alztw_n;                                      \
        uztw = ut; uzfw = uf; lztw = lt; lzfs = ls; lzfp = lp;                 \
        qs = qs_n; qi = qi_n; qgs = qgs_n; qgp = qgp_n;                        \
        o1 = o2;                                                               \
    } while (0)

    // ---- phase 1: warmup — no stores, no ET fold, unconditional prefetch ----
#pragma unroll 4
    for (int t = 0; t < SAC_WARMUP; ++t) {
        float2 cur = buf[t & (PF - 1)];
        buf[t & (PF - 1)] = *pe_pf;  pe_pf += B;
        SAC_BODY(cur, 0);
    }

    // ---- phase 2: main — unconditional stores AND prefetch; wide unroll ----
#pragma unroll 8
    for (int t = SAC_WARMUP; t < T - PF; ++t) {
        float2 cur = buf[t & (PF - 1)];
        buf[t & (PF - 1)] = *pe_pf;  pe_pf += B;
        SAC_BODY(cur, 1);
        *qout = o2;  qout += B;
        *eout = et;  eout += B;
    }

    // ---- phase 3: tail — last PF steps, no prefetch ----
#pragma unroll
    for (int t = T - PF; t < T; ++t) {
        float2 cur = buf[t & (PF - 1)];
        SAC_BODY(cur, 1);
        *qout = o2;  qout += B;
        *eout = et;  eout += B;
    }
#undef SAC_BODY
}

extern "C" void kernel_launch(void* const* d_in, const int* in_sizes, int n_in,
                              void* d_out, int out_size)
{
    const float* p_and_e = (const float*)d_in[0];   // [T, B, 2]
    const float* params  = (const float*)d_in[1];   // [B, 21]
    float* out = (float*)d_out;

    int B = in_sizes[1] / 21;
    int T = in_sizes[0] / (2 * B);

    int grid = (B + 127) / 128;
    if (B == 10000)
        sac4dpl_kernel<10000><<<grid, 128>>>(p_and_e, params, out, T, B);
    else
        sac4dpl_kernel<0><<<grid, 128>>>(p_and_e, params, out, T, B);
}

// round 14
// speedup vs baseline: 1.1014x; 1.1014x over previous
#include <cuda_runtime.h>
#include <math.h>

#define SAC_WARMUP 365
#define PF 4

__device__ __forceinline__ float fast_lg2(float x) {
    float r; asm("lg2.approx.f32 %0, %1;" : "=f"(r) : "f"(x)); return r;
}
__device__ __forceinline__ float fast_ex2(float x) {
    float r; asm("ex2.approx.f32 %0, %1;" : "=f"(r) : "f"(x)); return r;
}
__device__ __forceinline__ float fast_rcp(float d) {
    float r; asm("rcp.approx.f32 %0, %1;" : "=f"(r) : "f"(d));
    r = r * (2.0f - d * r);
    return r;
}

template <int BC>
__global__ __launch_bounds__(128, 1)
void sac4dpl_kernel(const float* __restrict__ p_and_e,   // [T, B, 2]
                    const float* __restrict__ params,    // [B, 21]
                    float* __restrict__ out,             // [2, T-WARMUP, B]
                    int T, int Brt)
{
    const int B = (BC > 0) ? BC : Brt;
    int b = blockIdx.x * 128 + threadIdx.x;
    if (b >= B) return;

    const float lo[21] = {0.1f, 0.0f, 0.0f, 10.0f, 10.0f, 50.0f, 10.0f, 50.0f,
                          0.0f, 0.0f, 0.0f, 5.0f, 1.0f, 0.1f, 0.01f, 0.001f,
                          0.5f, 0.95f, 0.98f, 0.0f, 0.0f};
    const float hi[21] = {1.2f, 0.1f, 0.3f, 100.0f, 100.0f, 400.0f, 100.0f, 1000.0f,
                          0.3f, 0.5f, 0.1f, 350.0f, 4.0f, 0.5f, 0.35f, 0.05f,
                          0.9f, 0.998f, 0.998f, 1.0f, 0.5f};
    float pr[21];
#pragma unroll
    for (int i = 0; i < 21; i++)
        pr[i] = lo[i] + params[(size_t)b * 21 + i] * (hi[i] - lo[i]);

    const float kc    = pr[0],  pctim = pr[1],  adimp = pr[2];
    const float uztwm = pr[3],  uzfwm = pr[4],  lztwm = pr[5];
    const float lzfsm = pr[6],  lzfpm = pr[7];
    const float pfree = pr[9],  riva  = pr[10];
    const float zperc = pr[11], rexp  = pr[12], uzk = pr[13];
    const float lzsk  = pr[14], lzpk  = pr[15];
    const float ci    = pr[16], cgs   = pr[17], cgp = pr[18];
    const float ke    = pr[19], xe    = pr[20];

    const float r_uztwm = 1.0f / uztwm;
    const float r_lztwm = 1.0f / lztwm;
    const float r_ulz   = 1.0f / (uztwm + lztwm);
    const float r_lzfsm = 1.0f / lzfsm;
    const float r_lzfpm = 1.0f / lzfpm;
    const float sfm     = lzfsm + lzfpm;
    const float lzsum   = sfm + lztwm;
    const float r_lzsum = 1.0f / lzsum;
    const float uzsum   = uztwm + uzfwm;
    const float pbase   = lzfsm * lzsk + lzfpm * lzpk;
    const float parea   = 1.0f - pctim - adimp;
    const float fp2     = 2.0f * (lzfpm / sfm);
    const float pbu     = pbase / uzfwm;
    const float pbuz    = pbu * zperc;
    const float ci1     = (1.0f - ci)  * parea;
    const float cgs1    = (1.0f - cgs) * parea;
    const float cgp1    = (1.0f - cgp) * parea;
    const float dt      = 0.5f;
    const float mden    = ke * (1.0f - xe) + dt;
    const float c1      = (ke * xe + dt) / mden;
    const float c2      = (dt - ke * xe) / mden;
    const float c3      = (ke * (1.0f - xe) - dt) / mden;

    // ---- initial carry ----
    float auztw = 0.01f, alztw = 0.01f;
    float uztw  = 0.01f, uzfw  = 0.01f;
    float lztw  = 0.01f, lzfs  = 0.01f, lzfp = 0.01f;
    float qs = 0.01f, qi = 0.01f, qgs = 0.01f, qgp = 0.01f;
    float o1 = 0.01f;
    float o2 = 0.01f, et = 0.01f;

    const float2* __restrict__ pe  = (const float2*)p_and_e + b;
    const int nout = T - SAC_WARMUP;
    float* __restrict__ qout = out + b;
    float* __restrict__ eout = out + (size_t)nout * B + b;

    float2 buf[PF];
#pragma unroll
    for (int i = 0; i < PF; i++)
        buf[i] = pe[(size_t)i * B];
    const float2* __restrict__ pe_pf = pe + (size_t)PF * B;

    // R10 body with exactly two deletion-only trims:
    //  - p/e clamps dropped (inputs uniform[0,20]/[0,6], provably >= 0)
    //  - ET fold computed only when DO_ET (store phase); main body otherwise
    //    identical to R10's (i1 recomputed from committed carries in the
    //    preamble — carried-i2 variant proved slower in R12/R13).
#define SAC_BODY(cur, DO_ET)                                                   \
    do {                                                                       \
        /* ---- carry-only preamble ---- */                                    \
        float uzw_sum = uztw + uzfw;                                           \
        float lzfsp   = lzfs + lzfp;                                           \
        float uma     = auztw - uztwm;                                         \
        float aru     = alztw * r_ulz;                                         \
        float lru     = lztw  * r_ulz;                                         \
        float sfm_l   = sfm   - lzfsp;                                         \
        float lzfpm_l = lzfpm - lzfp;                                          \
        float lzfsm_l = lzfsm - lzfs;                                          \
        float gp = 1.0f - lzfp * r_lzfpm;                                      \
        float gs = 1.0f - lzfs * r_lzfsm;                                      \
        float coef = fminf(fp2 * gp * fast_rcp(gp + gs), 1.0f);                \
        float i1   = (qs + qi) + (qgs + qgp);                                  \
        float mpre = c1 * i1 + c3 * o1;      /* o2 = c2*i2 + mpre */           \
        /* ---- input-dependent chain ---- */                                  \
        float p = (cur).x;                                                     \
        float e = (cur).y;                                                     \
        float ep    = kc * e;                                                  \
        float epru  = ep * r_uztwm;                                            \
        float roimp = pctim * p;                                               \
        float ae1   = fminf(auztw, epru * auztw);                              \
        float e1    = fminf(uztw,  epru * uztw);                               \
        float ae3   = (ep - ae1) * aru;                                        \
        float pav   = fmaxf((p + uma) - ae1, 0.0f);                            \
        float almae3 = alztw - ae3;                                            \
        float adsur = pav * (almae3 * r_lztwm);                                \
        float pam   = (pav - adsur) + almae3;                                  \
        float ars   = fmaxf(pam - lztwm, 0.0f);                                \
        float auztw_n = fminf(uztwm, (auztw - ae1) + p);                       \
        float alztw_n = fminf(lztwm, pam);                                     \
        float e2  = fminf(uzfw, ep - e1);                                      \
        float e12 = e1 + e2;                                                   \
        float e3  = (ep - e12) * lru;                                          \
        float lt1 = lztw - e3;                                                 \
        if (DO_ET) {                                                           \
            float ae2 = pctim * ep;                                            \
            float e4  = riva * ep;                                             \
            et = ((ae2 + ae1) + (ae3 + e1)) + ((e2 + e3) + e4);                \
        }                                                                      \
        float uzres = p + (uzw_sum - e12);                                     \
        float rs = fmaxf(uzres - uzsum, 0.0f) * parea;                         \
        float ut = fminf(uztwm, (uztw + p) - e1);                              \
        float uf = fminf(uzfwm, uzres - ut);                                   \
        float ri = uf * uzk;                                                   \
        uf = uf - ri;                                                          \
        float lzdef = lzfsp + lt1;                                             \
        float defr  = fmaxf(1.0f - lzdef * r_lzsum, 0.0f);                     \
        float pw    = fast_ex2(rexp * fast_lg2(defr));                         \
        float perc  = (pbu + pbuz * pw) * uf;                                  \
        float rate  = fminf(perc, lzsum - lzdef);                              \
        uf = fmaxf(uf - rate, 0.0f);                                           \
        float fx    = fminf(sfm_l,                                             \
                            fmaxf(rate - (lztwm - lt1), rate * pfree));        \
        float perct = rate - fx;                                               \
        float percp = fminf(lzfpm_l, fmaxf(fx - lzfsm_l, coef * fx));          \
        float percs = fx - percp;                                              \
        float lt = fminf(lt1 + perct, lztwm);                                  \
        float ls = lzfs + percs;                                               \
        float lp = lzfp + percp;                                               \
        float rgs = ls * lzsk;  ls = ls - rgs;                                 \
        float rgp = lp * lzpk;  lp = lp - rgp;                                 \
        float qs_n = (roimp + rs) + (adsur + ars) * adimp;                     \
        float qi_n = ci  * qi  + ci1  * ri;                                    \
        float qgs_n = cgs * qgs + cgs1 * rgs;                                  \
        float qgp_n = cgp * qgp + cgp1 * rgp;                                  \
        float i2   = (qs_n + qi_n) + (qgs_n + qgp_n);                          \
        o2 = c2 * i2 + mpre;                                                   \
        auztw = auztw_n; alztw = alztw_n;                                      \
        uztw = ut; uzfw = uf; lztw = lt; lzfs = ls; lzfp = lp;                 \
        qs = qs_n; qi = qi_n; qgs = qgs_n; qgp = qgp_n;                        \
        o1 = o2;                                                               \
    } while (0)

    // ---- phase 1: warmup — no stores, no ET fold, unconditional prefetch ----
#pragma unroll 4
    for (int t = 0; t < SAC_WARMUP; ++t) {
        float2 cur = buf[t & (PF - 1)];
        buf[t & (PF - 1)] = *pe_pf;  pe_pf += B;
        SAC_BODY(cur, 0);
    }

    // ---- phase 2: main — unconditional stores AND prefetch ----
#pragma unroll 4
    for (int t = SAC_WARMUP; t < T - PF; ++t) {
        float2 cur = buf[t & (PF - 1)];
        buf[t & (PF - 1)] = *pe_pf;  pe_pf += B;
        SAC_BODY(cur, 1);
        *qout = o2;  qout += B;
        *eout = et;  eout += B;
    }

    // ---- phase 3: tail — last PF steps, no prefetch ----
#pragma unroll
    for (int t = T - PF; t < T; ++t) {
        float2 cur = buf[t & (PF - 1)];
        SAC_BODY(cur, 1);
        *qout = o2;  qout += B;
        *eout = et;  eout += B;
    }
#undef SAC_BODY
}

extern "C" void kernel_launch(void* const* d_in, const int* in_sizes, int n_in,
                              void* d_out, int out_size)
{
    const float* p_and_e = (const float*)d_in[0];   // [T, B, 2]
    const float* params  = (const float*)d_in[1];   // [B, 21]
    float* out = (float*)d_out;

    int B = in_sizes[1] / 21;
    int T = in_sizes[0] / (2 * B);

    int grid = (B + 127) / 128;
    if (B == 10000)
        sac4dpl_kernel<10000><<<grid, 128>>>(p_and_e, params, out, T, B);
    else
        sac4dpl_kernel<0><<<grid, 128>>>(p_and_e, params, out, T, B);
}

// round 15
// speedup vs baseline: 1.1015x; 1.0001x over previous
#include <cuda_runtime.h>
#include <math.h>

#define SAC_WARMUP 365
#define PF 4

__device__ __forceinline__ float fast_lg2(float x) {
    float r; asm("lg2.approx.f32 %0, %1;" : "=f"(r) : "f"(x)); return r;
}
__device__ __forceinline__ float fast_ex2(float x) {
    float r; asm("ex2.approx.f32 %0, %1;" : "=f"(r) : "f"(x)); return r;
}
__device__ __forceinline__ float fast_rcp(float d) {
    float r; asm("rcp.approx.f32 %0, %1;" : "=f"(r) : "f"(d));
    r = r * (2.0f - d * r);
    return r;
}

template <int BC>
__global__ __launch_bounds__(128, 1)
void sac4dpl_kernel(const float* __restrict__ p_and_e,   // [T, B, 2]
                    const float* __restrict__ params,    // [B, 21]
                    float* __restrict__ out,             // [2, T-WARMUP, B]
                    int T, int Brt)
{
    const int B = (BC > 0) ? BC : Brt;
    int b = blockIdx.x * 128 + threadIdx.x;
    if (b >= B) return;

    const float lo[21] = {0.1f, 0.0f, 0.0f, 10.0f, 10.0f, 50.0f, 10.0f, 50.0f,
                          0.0f, 0.0f, 0.0f, 5.0f, 1.0f, 0.1f, 0.01f, 0.001f,
                          0.5f, 0.95f, 0.98f, 0.0f, 0.0f};
    const float hi[21] = {1.2f, 0.1f, 0.3f, 100.0f, 100.0f, 400.0f, 100.0f, 1000.0f,
                          0.3f, 0.5f, 0.1f, 350.0f, 4.0f, 0.5f, 0.35f, 0.05f,
                          0.9f, 0.998f, 0.998f, 1.0f, 0.5f};
    float pr[21];
#pragma unroll
    for (int i = 0; i < 21; i++)
        pr[i] = lo[i] + params[(size_t)b * 21 + i] * (hi[i] - lo[i]);

    const float kc    = pr[0],  pctim = pr[1],  adimp = pr[2];
    const float uztwm = pr[3],  uzfwm = pr[4],  lztwm = pr[5];
    const float lzfsm = pr[6],  lzfpm = pr[7];
    const float pfree = pr[9],  riva  = pr[10];
    const float zperc = pr[11], rexp  = pr[12], uzk = pr[13];
    const float lzsk  = pr[14], lzpk  = pr[15];
    const float ci    = pr[16], cgs   = pr[17], cgp = pr[18];
    const float ke    = pr[19], xe    = pr[20];

    const float r_uztwm = 1.0f / uztwm;
    const float r_lztwm = 1.0f / lztwm;
    const float r_ulz   = 1.0f / (uztwm + lztwm);
    const float r_lzfsm = 1.0f / lzfsm;
    const float r_lzfpm = 1.0f / lzfpm;
    const float sfm     = lzfsm + lzfpm;
    const float lzsum   = sfm + lztwm;
    const float r_lzsum = 1.0f / lzsum;
    const float uzsum   = uztwm + uzfwm;
    const float pbase   = lzfsm * lzsk + lzfpm * lzpk;
    const float parea   = 1.0f - pctim - adimp;
    const float fp2     = 2.0f * (lzfpm / sfm);
    const float pbu     = pbase / uzfwm;
    const float pbuz    = pbu * zperc;
    const float ci1     = (1.0f - ci)  * parea;
    const float cgs1    = (1.0f - cgs) * parea;
    const float cgp1    = (1.0f - cgp) * parea;
    const float dt      = 0.5f;
    const float mden    = ke * (1.0f - xe) + dt;
    const float c1      = (ke * xe + dt) / mden;
    const float c2      = (dt - ke * xe) / mden;
    const float c3      = (ke * (1.0f - xe) - dt) / mden;

    // ---- initial carry ----
    float auztw = 0.01f, alztw = 0.01f;
    float uztw  = 0.01f, uzfw  = 0.01f;
    float lztw  = 0.01f, lzfs  = 0.01f, lzfp = 0.01f;
    float qs = 0.01f, qi = 0.01f, qgs = 0.01f, qgp = 0.01f;
    float o1 = 0.01f;
    float o2 = 0.01f, et = 0.01f;

    const float2* __restrict__ pe  = (const float2*)p_and_e + b;
    const int nout = T - SAC_WARMUP;
    float* __restrict__ qout = out + b;
    float* __restrict__ eout = out + (size_t)nout * B + b;

    float2 buf[PF];
#pragma unroll
    for (int i = 0; i < PF; i++)
        buf[i] = pe[(size_t)i * B];
    const float2* __restrict__ pe_pf = pe + (size_t)PF * B;

    // DAG-widened step: carry-only preamble first (schedulable against the
    // input-dependent chain), tree-reassociated folds, shared ep*r_uztwm.
    // Clamp eliminations per R8 invariants; lg2 domain guard on defr kept.
#define SAC_BODY(cur)                                                          \
    do {                                                                       \
        /* ---- carry-only preamble: independent work for the scheduler ---- */\
        float uzw_sum = uztw + uzfw;                                           \
        float lzfsp   = lzfs + lzfp;                                           \
        float uma     = auztw - uztwm;                                         \
        float aru     = alztw * r_ulz;                                         \
        float lru     = lztw  * r_ulz;                                         \
        float sfm_l   = sfm   - lzfsp;                                         \
        float lzfpm_l = lzfpm - lzfp;                                          \
        float lzfsm_l = lzfsm - lzfs;                                          \
        float gp = 1.0f - lzfp * r_lzfpm;                                      \
        float gs = 1.0f - lzfs * r_lzfsm;                                      \
        float coef = fminf(fp2 * gp * fast_rcp(gp + gs), 1.0f);                \
        float i1   = (qs + qi) + (qgs + qgp);                                  \
        float mpre = c1 * i1 + c3 * o1;      /* o2 = c2*i2 + mpre */           \
        /* ---- input-dependent chain ---- */                                  \
        float p = fmaxf((cur).x, 0.0f);                                        \
        float e = fmaxf((cur).y, 0.0f);                                        \
        float ep    = kc * e;                                                  \
        float epru  = ep * r_uztwm;                                            \
        float roimp = pctim * p;                                               \
        float ae2   = pctim * ep;                                              \
        float ae1   = fminf(auztw, epru * auztw);                              \
        float e1    = fminf(uztw,  epru * uztw);                               \
        float ae3   = (ep - ae1) * aru;                                        \
        float pav   = fmaxf((p + uma) - ae1, 0.0f);                            \
        float almae3 = alztw - ae3;                                            \
        float adsur = pav * (almae3 * r_lztwm);                                \
        float pam   = (pav - adsur) + almae3;                                  \
        float ars   = fmaxf(pam - lztwm, 0.0f);                                \
        float auztw_n = fminf(uztwm, (auztw - ae1) + p);                       \
        float alztw_n = fminf(lztwm, pam);                                     \
        float e2  = fminf(uzfw, ep - e1);                                      \
        float e12 = e1 + e2;                                                   \
        float e3  = (ep - e12) * lru;                                          \
        float lt1 = lztw - e3;                                                 \
        float e4  = riva * ep;                                                 \
        et = ((ae2 + ae1) + (ae3 + e1)) + ((e2 + e3) + e4);                    \
        float uzres = p + (uzw_sum - e12);                                     \
        float rs = fmaxf(uzres - uzsum, 0.0f) * parea;                         \
        float ut = fminf(uztwm, (uztw + p) - e1);                              \
        float uf = fminf(uzfwm, uzres - ut);                                   \
        float ri = uf * uzk;                                                   \
        uf = uf - ri;                                                          \
        float lzdef = lzfsp + lt1;                                             \
        float defr  = fmaxf(1.0f - lzdef * r_lzsum, 0.0f);                     \
        float pw    = fast_ex2(rexp * fast_lg2(defr));                         \
        float perc  = (pbu + pbuz * pw) * uf;                                  \
        float rate  = fminf(perc, lzsum - lzdef);                              \
        uf = fmaxf(uf - rate, 0.0f);                                           \
        float fx    = fminf(sfm_l,                                             \
                            fmaxf(rate - (lztwm - lt1), rate * pfree));        \
        float perct = rate - fx;                                               \
        float percp = fminf(lzfpm_l, fmaxf(fx - lzfsm_l, coef * fx));          \
        float percs = fx - percp;                                              \
        float lt = fminf(lt1 + perct, lztwm);                                  \
        float ls = lzfs + percs;                                               \
        float lp = lzfp + percp;                                               \
        float rgs = ls * lzsk;  ls = ls - rgs;                                 \
        float rgp = lp * lzpk;  lp = lp - rgp;                                 \
        float qs_n = (roimp + rs) + (adsur + ars) * adimp;                     \
        float qi_n = ci  * qi  + ci1  * ri;                                    \
        float qgs_n = cgs * qgs + cgs1 * rgs;                                  \
        float qgp_n = cgp * qgp + cgp1 * rgp;                                  \
        float i2   = (qs_n + qi_n) + (qgs_n + qgp_n);                          \
        o2 = c2 * i2 + mpre;                                                   \
        auztw = auztw_n; alztw = alztw_n;                                      \
        uztw = ut; uzfw = uf; lztw = lt; lzfs = ls; lzfp = lp;                 \
        qs = qs_n; qi = qi_n; qgs = qgs_n; qgp = qgp_n;                        \
        o1 = o2;                                                               \
    } while (0)

    // ---- phase 1: warmup — no stores, unconditional prefetch ----
#pragma unroll 4
    for (int t = 0; t < SAC_WARMUP; ++t) {
        float2 cur = buf[t & (PF - 1)];
        buf[t & (PF - 1)] = *pe_pf;  pe_pf += B;
        SAC_BODY(cur);
    }

    // ---- phase 2: main — unconditional stores AND prefetch ----
#pragma unroll 4
    for (int t = SAC_WARMUP; t < T - PF; ++t) {
        float2 cur = buf[t & (PF - 1)];
        buf[t & (PF - 1)] = *pe_pf;  pe_pf += B;
        SAC_BODY(cur);
        *qout = o2;  qout += B;
        *eout = et;  eout += B;
    }

    // ---- phase 3: tail — last PF steps, no prefetch ----
#pragma unroll
    for (int t = T - PF; t < T; ++t) {
        float2 cur = buf[t & (PF - 1)];
        SAC_BODY(cur);
        *qout = o2;  qout += B;
        *eout = et;  eout += B;
    }
#undef SAC_BODY
}

extern "C" void kernel_launch(void* const* d_in, const int* in_sizes, int n_in,
                              void* d_out, int out_size)
{
    const float* p_and_e = (const float*)d_in[0];   // [T, B, 2]
    const float* params  = (const float*)d_in[1];   // [B, 21]
    float* out = (float*)d_out;

    int B = in_sizes[1] / 21;
    int T = in_sizes[0] / (2 * B);

    int grid = (B + 127) / 128;
    if (B == 10000)
        sac4dpl_kernel<10000><<<grid, 128>>>(p_and_e, params, out, T, B);
    else
        sac4dpl_kernel<0><<<grid, 128>>>(p_and_e, params, out, T, B);
}

// round 16
// speedup vs baseline: 1.1291x; 1.0250x over previous
#include <cuda_runtime.h>
#include <math.h>

#define SAC_WARMUP 365
#define PF 4

__device__ __forceinline__ float fast_lg2(float x) {
    float r; asm("lg2.approx.f32 %0, %1;" : "=f"(r) : "f"(x)); return r;
}
__device__ __forceinline__ float fast_ex2(float x) {
    float r; asm("ex2.approx.f32 %0, %1;" : "=f"(r) : "f"(x)); return r;
}
__device__ __forceinline__ float fast_rcp(float d) {
    float r; asm("rcp.approx.f32 %0, %1;" : "=f"(r) : "f"(d));
    r = r * (2.0f - d * r);
    return r;
}

template <int BC>
__global__ __launch_bounds__(128, 1)
void sac4dpl_kernel(const float* __restrict__ p_and_e,   // [T, B, 2]
                    const float* __restrict__ params,    // [B, 21]
                    float* __restrict__ out,             // [2, T-WARMUP, B]
                    int T, int Brt)
{
    const int B = (BC > 0) ? BC : Brt;
    int b = blockIdx.x * 128 + threadIdx.x;
    if (b >= B) return;

    const float lo[21] = {0.1f, 0.0f, 0.0f, 10.0f, 10.0f, 50.0f, 10.0f, 50.0f,
                          0.0f, 0.0f, 0.0f, 5.0f, 1.0f, 0.1f, 0.01f, 0.001f,
                          0.5f, 0.95f, 0.98f, 0.0f, 0.0f};
    const float hi[21] = {1.2f, 0.1f, 0.3f, 100.0f, 100.0f, 400.0f, 100.0f, 1000.0f,
                          0.3f, 0.5f, 0.1f, 350.0f, 4.0f, 0.5f, 0.35f, 0.05f,
                          0.9f, 0.998f, 0.998f, 1.0f, 0.5f};
    float pr[21];
#pragma unroll
    for (int i = 0; i < 21; i++)
        pr[i] = lo[i] + params[(size_t)b * 21 + i] * (hi[i] - lo[i]);

    const float kc    = pr[0],  pctim = pr[1],  adimp = pr[2];
    const float uztwm = pr[3],  uzfwm = pr[4],  lztwm = pr[5];
    const float lzfsm = pr[6],  lzfpm = pr[7];
    const float pfree = pr[9],  riva  = pr[10];
    const float zperc = pr[11], rexp  = pr[12], uzk = pr[13];
    const float lzsk  = pr[14], lzpk  = pr[15];
    const float ci    = pr[16], cgs   = pr[17], cgp = pr[18];
    const float ke    = pr[19], xe    = pr[20];

    const float r_uztwm = 1.0f / uztwm;
    const float r_lztwm = 1.0f / lztwm;
    const float r_ulz   = 1.0f / (uztwm + lztwm);
    const float r_lzfsm = 1.0f / lzfsm;
    const float r_lzfpm = 1.0f / lzfpm;
    const float sfm     = lzfsm + lzfpm;
    const float lzsum   = sfm + lztwm;
    const float r_lzsum = 1.0f / lzsum;
    const float uzsum   = uztwm + uzfwm;
    const float pbase   = lzfsm * lzsk + lzfpm * lzpk;
    const float parea   = 1.0f - pctim - adimp;
    const float fp2     = 2.0f * (lzfpm / sfm);
    const float pbu     = pbase / uzfwm;
    const float pbuz    = pbu * zperc;
    const float ci1     = (1.0f - ci)  * parea;
    const float cgs1    = (1.0f - cgs) * parea;
    const float cgp1    = (1.0f - cgp) * parea;
    const float dt      = 0.5f;
    const float mden    = ke * (1.0f - xe) + dt;
    const float c1      = (ke * xe + dt) / mden;
    const float c2      = (dt - ke * xe) / mden;
    const float c3      = (ke * (1.0f - xe) - dt) / mden;

    // ---- initial carry ----
    float auztw = 0.01f, alztw = 0.01f;
    float uztw  = 0.01f, uzfw  = 0.01f;
    float lztw  = 0.01f, lzfs  = 0.01f, lzfp = 0.01f;
    float qs = 0.01f, qi = 0.01f, qgs = 0.01f, qgp = 0.01f;
    float o1 = 0.01f;
    float o2 = 0.01f, et = 0.01f;

    const float2* __restrict__ pe  = (const float2*)p_and_e + b;
    const int nout = T - SAC_WARMUP;
    float* __restrict__ qout = out + b;
    float* __restrict__ eout = out + (size_t)nout * B + b;

    float2 buf[PF];
#pragma unroll
    for (int i = 0; i < PF; i++)
        buf[i] = pe[(size_t)i * B];
    const float2* __restrict__ pe_pf = pe + (size_t)PF * B;

    // DAG-widened step: carry-only preamble first (schedulable against the
    // input-dependent chain), tree-reassociated folds, shared ep*r_uztwm.
    // Clamp eliminations per R8 invariants; lg2 domain guard on defr kept.
#define SAC_BODY(cur)                                                          \
    do {                                                                       \
        /* ---- carry-only preamble: independent work for the scheduler ---- */\
        float uzw_sum = uztw + uzfw;                                           \
        float lzfsp   = lzfs + lzfp;                                           \
        float uma     = auztw - uztwm;                                         \
        float aru     = alztw * r_ulz;                                         \
        float lru     = lztw  * r_ulz;                                         \
        float sfm_l   = sfm   - lzfsp;                                         \
        float lzfpm_l = lzfpm - lzfp;                                          \
        float lzfsm_l = lzfsm - lzfs;                                          \
        float gp = 1.0f - lzfp * r_lzfpm;                                      \
        float gs = 1.0f - lzfs * r_lzfsm;                                      \
        float coef = fminf(fp2 * gp * fast_rcp(gp + gs), 1.0f);                \
        float i1   = (qs + qi) + (qgs + qgp);                                  \
        float mpre = c1 * i1 + c3 * o1;      /* o2 = c2*i2 + mpre */           \
        /* ---- input-dependent chain ---- */                                  \
        float p = fmaxf((cur).x, 0.0f);                                        \
        float e = fmaxf((cur).y, 0.0f);                                        \
        float ep    = kc * e;                                                  \
        float epru  = ep * r_uztwm;                                            \
        float roimp = pctim * p;                                               \
        float ae2   = pctim * ep;                                              \
        float ae1   = fminf(auztw, epru * auztw);                              \
        float e1    = fminf(uztw,  epru * uztw);                               \
        float ae3   = (ep - ae1) * aru;                                        \
        float pav   = fmaxf((p + uma) - ae1, 0.0f);                            \
        float almae3 = alztw - ae3;                                            \
        float adsur = pav * (almae3 * r_lztwm);                                \
        float pam   = (pav - adsur) + almae3;                                  \
        float ars   = fmaxf(pam - lztwm, 0.0f);                                \
        float auztw_n = fminf(uztwm, (auztw - ae1) + p);                       \
        float alztw_n = fminf(lztwm, pam);                                     \
        float e2  = fminf(uzfw, ep - e1);                                      \
        float e12 = e1 + e2;                                                   \
        float e3  = (ep - e12) * lru;                                          \
        float lt1 = lztw - e3;                                                 \
        float e4  = riva * ep;                                                 \
        et = ((ae2 + ae1) + (ae3 + e1)) + ((e2 + e3) + e4);                    \
        float uzres = p + (uzw_sum - e12);                                     \
        float rs = fmaxf(uzres - uzsum, 0.0f) * parea;                         \
        float ut = fminf(uztwm, (uztw + p) - e1);                              \
        float uf = fminf(uzfwm, uzres - ut);                                   \
        float ri = uf * uzk;                                                   \
        uf = uf - ri;                                                          \
        float lzdef = lzfsp + lt1;                                             \
        float defr  = fmaxf(1.0f - lzdef * r_lzsum, 0.0f);                     \
        float pw    = fast_ex2(rexp * fast_lg2(defr));                         \
        float perc  = (pbu + pbuz * pw) * uf;                                  \
        float rate  = fminf(perc, lzsum - lzdef);                              \
        uf = fmaxf(uf - rate, 0.0f);                                           \
        float fx    = fminf(sfm_l,                                             \
                            fmaxf(rate - (lztwm - lt1), rate * pfree));        \
        float perct = rate - fx;                                               \
        float percp = fminf(lzfpm_l, fmaxf(fx - lzfsm_l, coef * fx));          \
        float percs = fx - percp;                                              \
        float lt = fminf(lt1 + perct, lztwm);                                  \
        float ls = lzfs + percs;                                               \
        float lp = lzfp + percp;                                               \
        float rgs = ls * lzsk;  ls = ls - rgs;                                 \
        float rgp = lp * lzpk;  lp = lp - rgp;                                 \
        float qs_n = (roimp + rs) + (adsur + ars) * adimp;                     \
        float qi_n = ci  * qi  + ci1  * ri;                                    \
        float qgs_n = cgs * qgs + cgs1 * rgs;                                  \
        float qgp_n = cgp * qgp + cgp1 * rgp;                                  \
        float i2   = (qs_n + qi_n) + (qgs_n + qgp_n);                          \
        o2 = c2 * i2 + mpre;                                                   \
        auztw = auztw_n; alztw = alztw_n;                                      \
        uztw = ut; uzfw = uf; lztw = lt; lzfs = ls; lzfp = lp;                 \
        qs = qs_n; qi = qi_n; qgs = qgs_n; qgp = qgp_n;                        \
        o1 = o2;                                                               \
    } while (0)

    // ---- phase 1: warmup — no stores, unconditional prefetch ----
#pragma unroll 4
    for (int t = 0; t < SAC_WARMUP; ++t) {
        float2 cur = buf[t & (PF - 1)];
        buf[t & (PF - 1)] = *pe_pf;  pe_pf += B;
        SAC_BODY(cur);
    }

    // ---- phase 2: main — unconditional stores AND prefetch ----
#pragma unroll 4
    for (int t = SAC_WARMUP; t < T - PF; ++t) {
        float2 cur = buf[t & (PF - 1)];
        buf[t & (PF - 1)] = *pe_pf;  pe_pf += B;
        SAC_BODY(cur);
        *qout = o2;  qout += B;
        *eout = et;  eout += B;
    }

    // ---- phase 3: tail — last PF steps, no prefetch ----
#pragma unroll
    for (int t = T - PF; t < T; ++t) {
        float2 cur = buf[t & (PF - 1)];
        SAC_BODY(cur);
        *qout = o2;  qout += B;
        *eout = et;  eout += B;
    }
#undef SAC_BODY
}

extern "C" void kernel_launch(void* const* d_in, const int* in_sizes, int n_in,
                              void* d_out, int out_size)
{
    const float* p_and_e = (const float*)d_in[0];   // [T, B, 2]
    const float* params  = (const float*)d_in[1];   // [B, 21]
    float* out = (float*)d_out;

    int B = in_sizes[1] / 21;
    int T = in_sizes[0] / (2 * B);

    int grid = (B + 127) / 128;
    if (B == 10000)
        sac4dpl_kernel<10000><<<grid, 128>>>(p_and_e, params, out, T, B);
    else
        sac4dpl_kernel<0><<<grid, 128>>>(p_and_e, params, out, T, B);
}